// round 8
// baseline (speedup 1.0000x reference)
#include <cuda_runtime.h>

#define BB 2
#define HH 160
#define WW 160
#define NPTS 2048
#define HW (HH*WW)
#define TOTAL (BB*HW)        // 51200
#define NV4 (TOTAL/4)        // 12800 float4s
#define NTHR 1024
#define NBLK 13              // 13*1024 float4s = 53248 slots >= 51200 pixels
#define PIX_PER_BLK (NTHR*4) // 4096 pixels per block slice
#define NPT (BB*NPTS)        // 4096 points
#define LMASKW (PIX_PER_BLK/32)  // 128 words = 512 B local mask
#define DOWN 16.0f
#define HALF 7.5f
#define INV  (1.0f/16.0f)

__device__ float    g_partials[NBLK];
__device__ unsigned g_count;   // zero-init; acq_rel inc wraps -> self-resets each replay

__device__ __forceinline__ float warp_sum(float v) {
    #pragma unroll
    for (int o = 16; o > 0; o >>= 1) v += __shfl_down_sync(0xffffffffu, v, o);
    return v;
}

// softplus(a) = max(a,0) + log1p(exp(-|a|)); fast fp32 MUFU version
__device__ __forceinline__ float softplus(float a) {
    return fmaxf(a, 0.0f) + __logf(1.0f + __expf(-fabsf(a)));
}

// acq_rel atomicInc: orders this block's prior store (release) and the last
// arrival's subsequent loads (acquire) without a full MEMBAR.GPU / L1 flush.
__device__ __forceinline__ unsigned atomicInc_acqrel(unsigned* p, unsigned b) {
    unsigned old;
    asm volatile("atom.acq_rel.gpu.global.inc.u32 %0, [%1], %2;"
                 : "=r"(old) : "l"(p), "r"(b) : "memory");
    return old;
}

// branchless nearest pixel-center index along one axis (exact: the 2nd-nearest
// center is >= 8 away on that axis, so only the nearest can pass dist < 8)
__device__ __forceinline__ float nearest_center(float p, float lim) {
    float fi = floorf((p - HALF) * INV);
    float d0 = fmaf(fi, DOWN, HALF) - p;
    fi = (fabsf(d0) <= fabsf(d0 + DOWN)) ? fi : fi + 1.0f;
    return fminf(fmaxf(fi, 0.0f), lim);
}

__global__ __launch_bounds__(NTHR, 1)
void p2r_fused(const float* __restrict__ dens, const float* __restrict__ pts,
               float* __restrict__ out) {
    __shared__ float    s_red[NTHR / 32];
    __shared__ unsigned s_mask[LMASKW];   // bit per pixel of THIS block's slice

    const int tid  = threadIdx.x;
    const int lane = tid & 31;
    const int w    = tid >> 5;
    const int bid  = blockIdx.x;

    // ---- issue this thread's dense load (1 float4 = 4 pixels) immediately ----
    const int fi = bid * NTHR + tid;
    const bool valid = fi < NV4;
    float4 a = valid ? ((const float4*)dens)[fi] : make_float4(0.f, 0.f, 0.f, 0.f);

    // ---- issue point loads (all 4096 points, 4 per thread; L2-hot) ----
    const float4* p4 = (const float4*)pts;   // 2 points per float4
    float4 pp0 = p4[2 * tid];
    float4 pp1 = p4[2 * tid + 1];

    // zero local mask while loads are in flight, then BARRIER before any
    // atomicOr touches it (this sync was missing in R6 -> lost marks)
    if (tid < LMASKW) s_mask[tid] = 0u;
    __syncthreads();

    // ---- rasterize: mark points whose nearest pixel falls in MY slice ----
    const int  b    = tid >> 9;             // points 4t..4t+3 share batch
    const int  base = bid * PIX_PER_BLK;    // my slice: [base, base+4096)
    #pragma unroll
    for (int q = 0; q < 2; q++) {
        const float4 pq = q ? pp1 : pp0;
        #pragma unroll
        for (int h = 0; h < 2; h++) {
            const float p0 = h ? pq.z : pq.x;   // y
            const float p1 = h ? pq.w : pq.y;   // x
            const float fy = nearest_center(p0, (float)(HH - 1));
            const float fx = nearest_center(p1, (float)(WW - 1));
            const float dy = fmaf(fy, DOWN, HALF) - p0;
            const float dx = fmaf(fx, DOWN, HALF) - p1;
            // sqrtf(d2) < 8  <=>  d2 < 64 (sqrt monotone, correctly rounded)
            const int idx = b * HW + (int)fy * WW + (int)fx;
            const int off = idx - base;
            if ((dy * dy + dx * dx) < 64.0f && (unsigned)off < PIX_PER_BLK)
                atomicOr(&s_mask[off >> 5], 1u << (off & 31));  // same-value races OK
        }
    }
    __syncthreads();

    // ---- fold: v = softplus(A) + [marked]*(softplus(A) - 2A) over my 4 pixels ----
    float v = 0.0f;
    if (valid) {
        const unsigned m = s_mask[tid >> 3] >> ((tid & 7) * 4);  // my 4 bits
        float sp;
        sp = softplus(a.x); v += sp + ((m & 1u) ? sp - 2.0f * a.x : 0.0f);
        sp = softplus(a.y); v += sp + ((m & 2u) ? sp - 2.0f * a.y : 0.0f);
        sp = softplus(a.z); v += sp + ((m & 4u) ? sp - 2.0f * a.z : 0.0f);
        sp = softplus(a.w); v += sp + ((m & 8u) ? sp - 2.0f * a.w : 0.0f);
    }

    // ---- block reduce -> one L2 store + one acq_rel atomic per block ----
    v = warp_sum(v);
    if (lane == 0) s_red[w] = v;
    __syncthreads();
    if (w != 0) return;
    v = warp_sum(s_red[lane]);

    unsigned old = 0;
    if (lane == 0) {
        __stcg(&g_partials[bid], v);                  // straight to L2
        old = atomicInc_acqrel(&g_count, NBLK - 1);   // wraps to 0 on last
    }
    old = __shfl_sync(0xffffffffu, old, 0);
    if (old == NBLK - 1) {
        float p = (lane < NBLK) ? __ldcg(&g_partials[lane]) : 0.0f;
        p = warp_sum(p);
        if (lane == 0) out[0] = p * (1.0f / (float)TOTAL);
    }
}

extern "C" void kernel_launch(void* const* d_in, const int* in_sizes, int n_in,
                              void* d_out, int out_size) {
    const float* dens = (const float*)d_in[0];
    const float* pts  = (const float*)d_in[1];
    p2r_fused<<<NBLK, NTHR>>>(dens, pts, (float*)d_out);
}